// round 4
// baseline (speedup 1.0000x reference)
#include <cuda_runtime.h>
#include <cuda_bf16.h>
#include <cstdint>

#define NN 10000
#define MPAD 10112        // 79 * 128
#define NT 79
#define EE 320000
#define CC 256
#define LL 3
#define DD 20
#define GAMMA 0.705078125f       // 0.125 / interval^2, interval = 8/19
#define KAF_C1 0.59375f          // 2*gamma*interval = 0.25/interval
#define KAF_Q  0.778800783f      // exp(-0.25)

// ---------------- scratch (device globals) ----------------
__device__ float g_hw[NN * CC];
__device__ uint32_t g_hnb[NN * 128];            // hn as bf16x2 pairs
__device__ int   g_deg[NN];
__device__ int   g_off[NN + 1];
__device__ int   g_cursor[NN];
__device__ int   g_slot[EE];
__device__ float g_sea0[NN];
__device__ float g_sea1[NN];
__device__ __align__(16) __nv_bfloat16 gA_hi[MPAD * CC];
__device__ __align__(16) __nv_bfloat16 gA_lo[MPAD * CC];
__device__ __align__(16) __nv_bfloat16 gB_hi[LL * 512 * CC];  // [l][n][k]: n<256 neigh_w, else node_w
__device__ __align__(16) __nv_bfloat16 gB_lo[LL * 512 * CC];

// ---------------- setup kernels ----------------
__global__ void k_zero() {
    int i = blockIdx.x * blockDim.x + threadIdx.x;
    if (i < NN) { g_deg[i] = 0; g_cursor[i] = 0; g_sea0[i] = 0.f; g_sea1[i] = 0.f; }
}

__global__ void k_count(const int* __restrict__ ei) {
    int e = blockIdx.x * blockDim.x + threadIdx.x;
    if (e < EE) atomicAdd(&g_deg[ei[EE + e]], 1);
}

__global__ void k_scan() {
    __shared__ int sh[1024];
    __shared__ int s_carry;
    int tid = threadIdx.x;
    if (tid == 0) s_carry = 0;
    __syncthreads();
    for (int base = 0; base < NN; base += 1024) {
        int carry = s_carry;
        int i = base + tid;
        int v = (i < NN) ? g_deg[i] : 0;
        int sum = v;
        sh[tid] = v;
        __syncthreads();
        #pragma unroll
        for (int s = 1; s < 1024; s <<= 1) {
            int t = (tid >= s) ? sh[tid - s] : 0;
            __syncthreads();
            sum += t;
            sh[tid] = sum;
            __syncthreads();
        }
        if (i < NN) g_off[i] = carry + sum - v;
        __syncthreads();
        if (tid == 1023) s_carry = carry + sh[1023];
        __syncthreads();
    }
    if (tid == 0) g_off[NN] = s_carry;
}

__global__ void k_scatter(const int* __restrict__ ei, const float* __restrict__ ea) {
    int e = blockIdx.x * blockDim.x + threadIdx.x;
    if (e < EE) {
        int src = ei[e];
        int dst = ei[EE + e];
        int pos = g_off[dst] + atomicAdd(&g_cursor[dst], 1);
        g_slot[pos] = src;
        atomicAdd(&g_sea0[dst], ea[2 * e]);
        atomicAdd(&g_sea1[dst], ea[2 * e + 1]);
    }
}

// x -> gA_hi/gA_lo (padding rows zeroed)
__global__ void k_split_x(const float* __restrict__ h) {
    int i = blockIdx.x * blockDim.x + threadIdx.x;
    if (i < MPAD * CC) {
        float v = (i < NN * CC) ? h[i] : 0.0f;
        __nv_bfloat16 hi = __float2bfloat16_rn(v);
        __nv_bfloat16 lo = __float2bfloat16_rn(v - __bfloat162float(hi));
        gA_hi[i] = hi;
        gA_lo[i] = lo;
    }
}

// all-layer B_cat split
__global__ void k_prep_B(const float* __restrict__ nw, const float* __restrict__ ow) {
    int i = blockIdx.x * blockDim.x + threadIdx.x;
    if (i < LL * 512 * CC) {
        int l = i / (512 * CC);
        int r = i - l * 512 * CC;
        int n = r >> 8, k = r & 255;
        float v = (n < CC) ? nw[l * CC * CC + k * CC + n]
                           : ow[l * CC * CC + k * CC + (n - CC)];
        __nv_bfloat16 hi = __float2bfloat16_rn(v);
        __nv_bfloat16 lo = __float2bfloat16_rn(v - __bfloat162float(hi));
        gB_hi[i] = hi;
        gB_lo[i] = lo;
    }
}

// ---------------- HMMA GEMM ----------------
#define SW128(x) ((x) ^ (((x) >> 3) & 0x70))

__device__ __forceinline__ uint32_t s2u(const void* p) {
    uint32_t a;
    asm("{ .reg .u64 t; cvta.to.shared.u64 t, %1; cvt.u32.u64 %0, t; }" : "=r"(a) : "l"(p));
    return a;
}

__device__ __forceinline__ void ldsm_x4(uint32_t& r0, uint32_t& r1, uint32_t& r2, uint32_t& r3,
                                        uint32_t addr) {
    asm volatile("ldmatrix.sync.aligned.m8n8.x4.shared.b16 {%0,%1,%2,%3}, [%4];"
                 : "=r"(r0), "=r"(r1), "=r"(r2), "=r"(r3) : "r"(addr));
}

__device__ __forceinline__ void mma16816(float* c, const uint32_t* a, const uint32_t* b) {
    asm volatile(
        "mma.sync.aligned.m16n8k16.row.col.f32.bf16.bf16.f32 "
        "{%0,%1,%2,%3}, {%4,%5,%6,%7}, {%8,%9}, {%0,%1,%2,%3};"
        : "+f"(c[0]), "+f"(c[1]), "+f"(c[2]), "+f"(c[3])
        : "r"(a[0]), "r"(a[1]), "r"(a[2]), "r"(a[3]), "r"(b[0]), "r"(b[1]));
}

__device__ __forceinline__ uint32_t packbf2(float a, float b) {
    __nv_bfloat162 t = __float22bfloat162_rn(make_float2(a, b));
    return *reinterpret_cast<uint32_t*>(&t);
}

#define TB 16384
#define SMEM_TOTAL (4 * TB)

// grid (79, 4): tile [bx*128, by*128] of [MPAD, 512]; cols<256 -> g_hnb (bf16), cols>=256 -> g_hw (fp32)
__global__ __launch_bounds__(256) void k_gemm_tc(int layer) {
    extern __shared__ char smem[];
    char* sAhi = smem;
    char* sAlo = smem + TB;
    char* sBhi = smem + 2 * TB;
    char* sBlo = smem + 3 * TB;
    uint32_t ubase = s2u(smem);

    const __nv_bfloat16* Bhi = gB_hi + layer * 512 * CC;
    const __nv_bfloat16* Blo = gB_lo + layer * 512 * CC;

    int tid = threadIdx.x, wid = tid >> 5, lid = tid & 31;
    int m0 = blockIdx.x * 128;
    int nblk = blockIdx.y;
    int warp_m = (wid & 3) * 32;
    int warp_n = (wid >> 2) * 64;

    float acc[2][8][4];
    #pragma unroll
    for (int t = 0; t < 2; t++)
        #pragma unroll
        for (int n = 0; n < 8; n++)
            #pragma unroll
            for (int j = 0; j < 4; j++) acc[t][n][j] = 0.f;

    int g = lid >> 3, rid = lid & 7;

    for (int ch = 0; ch < 4; ch++) {
        int kg = ch * 64;
        #pragma unroll
        for (int it = 0; it < 4; it++) {
            int i = tid + it * 256;
            int r = i >> 3, c = i & 7;
            uint32_t so = SW128((uint32_t)(r * 128 + c * 16));
            int ga = (m0 + r) * CC + kg + c * 8;
            int gb = (nblk * 128 + r) * CC + kg + c * 8;
            *(uint4*)(sAhi + so) = *(const uint4*)&gA_hi[ga];
            *(uint4*)(sAlo + so) = *(const uint4*)&gA_lo[ga];
            *(uint4*)(sBhi + so) = *(const uint4*)&Bhi[gb];
            *(uint4*)(sBlo + so) = *(const uint4*)&Blo[gb];
        }
        __syncthreads();

        #pragma unroll
        for (int pass = 0; pass < 3; pass++) {
            uint32_t ua = ubase + ((pass == 2) ? TB : 0);
            uint32_t ub = ubase + ((pass == 1) ? 3 * TB : 2 * TB);
            #pragma unroll
            for (int ks = 0; ks < 4; ks++) {
                int kc2 = ks * 2;
                uint32_t a[2][4];
                #pragma unroll
                for (int t = 0; t < 2; t++) {
                    int row = warp_m + t * 16 + ((g & 1) ? 8 : 0) + rid;
                    int chunk = kc2 + (g >> 1);
                    ldsm_x4(a[t][0], a[t][1], a[t][2], a[t][3],
                            ua + SW128((uint32_t)(row * 128 + chunk * 16)));
                }
                uint32_t b[8][2];
                #pragma unroll
                for (int p = 0; p < 4; p++) {
                    int row = warp_n + p * 16 + ((g >> 1) ? 8 : 0) + rid;
                    int chunk = kc2 + (g & 1);
                    ldsm_x4(b[2 * p][0], b[2 * p][1], b[2 * p + 1][0], b[2 * p + 1][1],
                            ub + SW128((uint32_t)(row * 128 + chunk * 16)));
                }
                #pragma unroll
                for (int t = 0; t < 2; t++)
                    #pragma unroll
                    for (int n = 0; n < 8; n++)
                        mma16816(acc[t][n], a[t], b[n]);
            }
        }
        __syncthreads();
    }

    int qm = lid >> 2, qn = (lid & 3) * 2;
    #pragma unroll
    for (int t = 0; t < 2; t++) {
        #pragma unroll
        for (int n = 0; n < 8; n++) {
            int row0 = m0 + warp_m + t * 16 + qm;
            int colg = nblk * 128 + warp_n + n * 8 + qn;
            if (colg < 256) {
                if (row0 < NN)
                    g_hnb[row0 * 128 + (colg >> 1)] = packbf2(acc[t][n][0], acc[t][n][1]);
                if (row0 + 8 < NN)
                    g_hnb[(row0 + 8) * 128 + (colg >> 1)] = packbf2(acc[t][n][2], acc[t][n][3]);
            } else {
                int col = colg - 256;
                if (row0 < NN)
                    *(float2*)&g_hw[row0 * CC + col] = make_float2(acc[t][n][0], acc[t][n][1]);
                if (row0 + 8 < NN)
                    *(float2*)&g_hw[(row0 + 8) * CC + col] = make_float2(acc[t][n][2], acc[t][n][3]);
            }
        }
    }
}

// ---------------- warp-per-node aggregation + KAF + split for next layer ----------------
__device__ __forceinline__ void add8(float* acc, uint4 v) {
    uint32_t w[4] = {v.x, v.y, v.z, v.w};
    #pragma unroll
    for (int u = 0; u < 4; u++) {
        acc[2 * u]     += __uint_as_float(w[u] << 16);
        acc[2 * u + 1] += __uint_as_float(w[u] & 0xFFFF0000u);
    }
}

__global__ __launch_bounds__(256) void k_aggr_kaf(const float* __restrict__ ew,
                                                  const float* __restrict__ bias,
                                                  const float* __restrict__ alpha,
                                                  float* __restrict__ out, int last) {
    int n = blockIdx.x * 8 + (threadIdx.x >> 5);
    if (n >= NN) return;
    int lane = threadIdx.x & 31;
    int o0 = g_off[n], o1 = g_off[n + 1];
    int deg = o1 - o0;
    int col = lane * 4;   // uint index within row

    float acc[8];
    #pragma unroll
    for (int k = 0; k < 8; k++) acc[k] = 0.f;

    int e = o0;
    for (; e + 4 <= o1; e += 4) {
        int s0 = g_slot[e], s1 = g_slot[e + 1], s2 = g_slot[e + 2], s3 = g_slot[e + 3];
        uint4 v0 = *(const uint4*)&g_hnb[s0 * 128 + col];
        uint4 v1 = *(const uint4*)&g_hnb[s1 * 128 + col];
        uint4 v2 = *(const uint4*)&g_hnb[s2 * 128 + col];
        uint4 v3 = *(const uint4*)&g_hnb[s3 * 128 + col];
        add8(acc, v0); add8(acc, v1); add8(acc, v2); add8(acc, v3);
    }
    for (; e < o1; e++) {
        int s = g_slot[e];
        uint4 v = *(const uint4*)&g_hnb[s * 128 + col];
        add8(acc, v);
    }

    float inv = (deg > 0) ? 1.0f / (float)deg : 0.0f;
    float sea0 = g_sea0[n] * inv, sea1 = g_sea1[n] * inv;

    int ch0 = lane * 8;
    float4 hwa = *(const float4*)&g_hw[n * CC + ch0];
    float4 hwb = *(const float4*)&g_hw[n * CC + ch0 + 4];
    float hw[8] = {hwa.x, hwa.y, hwa.z, hwa.w, hwb.x, hwb.y, hwb.z, hwb.w};

    float res[8];
    #pragma unroll
    for (int k = 0; k < 8; k++) {
        int c = ch0 + k;
        float s = acc[k] * inv + sea0 * ew[c] + sea1 * ew[CC + c] + hw[k] + bias[c];
        // KAF via multiplicative recurrence: K_{d+1} = K_d * r, r *= q
        float u0 = s + 4.0f;
        float K = __expf(-GAMMA * u0 * u0);
        float r = __expf(KAF_C1 * u0 - 0.125f);
        const float4* ap = (const float4*)&alpha[c * DD];
        float t = 0.f;
        #pragma unroll
        for (int v5 = 0; v5 < 5; v5++) {
            float4 a4 = ap[v5];
            t += a4.x * K; K *= r; r *= KAF_Q;
            t += a4.y * K; K *= r; r *= KAF_Q;
            t += a4.z * K; K *= r; r *= KAF_Q;
            t += a4.w * K; K *= r; r *= KAF_Q;
        }
        res[k] = t;
    }

    if (last) {
        *(float4*)&out[n * CC + ch0]     = make_float4(res[0], res[1], res[2], res[3]);
        *(float4*)&out[n * CC + ch0 + 4] = make_float4(res[4], res[5], res[6], res[7]);
    } else {
        uint32_t hi[4], lo[4];
        #pragma unroll
        for (int u = 0; u < 4; u++) {
            __nv_bfloat16 h0 = __float2bfloat16_rn(res[2 * u]);
            __nv_bfloat16 h1 = __float2bfloat16_rn(res[2 * u + 1]);
            __nv_bfloat16 l0 = __float2bfloat16_rn(res[2 * u] - __bfloat162float(h0));
            __nv_bfloat16 l1 = __float2bfloat16_rn(res[2 * u + 1] - __bfloat162float(h1));
            hi[u] = ((uint32_t)*(uint16_t*)&h1 << 16) | *(uint16_t*)&h0;
            lo[u] = ((uint32_t)*(uint16_t*)&l1 << 16) | *(uint16_t*)&l0;
        }
        *(uint4*)&gA_hi[n * CC + ch0] = make_uint4(hi[0], hi[1], hi[2], hi[3]);
        *(uint4*)&gA_lo[n * CC + ch0] = make_uint4(lo[0], lo[1], lo[2], lo[3]);
    }
}

// ---------------- launch ----------------
extern "C" void kernel_launch(void* const* d_in, const int* in_sizes, int n_in,
                              void* d_out, int out_size) {
    const float* x       = (const float*)d_in[0];
    const int*   ei      = (const int*)d_in[1];
    const float* ea      = (const float*)d_in[2];
    const float* node_w  = (const float*)d_in[3];
    const float* edge_w  = (const float*)d_in[4];
    const float* neigh_w = (const float*)d_in[5];
    const float* bias    = (const float*)d_in[6];
    const float* alpha   = (const float*)d_in[7];
    float* out = (float*)d_out;

    cudaFuncSetAttribute(k_gemm_tc, cudaFuncAttributeMaxDynamicSharedMemorySize, SMEM_TOTAL);

    // graph-structure setup + input splits
    k_zero<<<(NN + 255) / 256, 256>>>();
    k_count<<<(EE + 255) / 256, 256>>>(ei);
    k_scan<<<1, 1024>>>();
    k_scatter<<<(EE + 255) / 256, 256>>>(ei, ea);
    k_split_x<<<(MPAD * CC + 255) / 256, 256>>>(x);
    k_prep_B<<<(LL * 512 * CC + 255) / 256, 256>>>(neigh_w, node_w);

    dim3 gg(NT, 4);
    for (int l = 0; l < LL; l++) {
        k_gemm_tc<<<gg, 256, SMEM_TOTAL>>>(l);
        k_aggr_kaf<<<NN / 8, 256>>>(edge_w + l * 2 * CC, bias + l * CC,
                                    alpha + l * CC * DD, out, (l == LL - 1) ? 1 : 0);
    }
}

// round 5
// speedup vs baseline: 1.2407x; 1.2407x over previous
#include <cuda_runtime.h>
#include <cuda_fp16.h>
#include <cuda_bf16.h>
#include <cstdint>

#define NN 10000
#define MPAD 10112        // 79 * 128
#define NT 79
#define EE 320000
#define CC 256
#define LL 3
#define DD 20
#define GAMMA 0.705078125f       // 0.125 / interval^2, interval = 8/19
#define KAF_C1 0.59375f          // 2*gamma*interval
#define KAF_Q  0.778800783f      // exp(-0.25)

// ---------------- scratch (device globals) ----------------
__device__ float g_hw[NN * CC];
__device__ uint32_t g_hnb[NN * 128];            // hn as bf16x2 pairs
__device__ int   g_deg[NN];
__device__ int   g_off[NN + 1];
__device__ int   g_cursor[NN];
__device__ int   g_slot[EE];
__device__ float g_sea0[NN];
__device__ float g_sea1[NN];
__device__ __align__(16) __half gA_hi[MPAD * CC];
__device__ __align__(16) __half gA_lo[MPAD * CC];
__device__ __align__(16) __half gB[LL * 512 * CC];  // [l][n][k]: n<256 neigh_w, else node_w

// ---------------- setup kernels ----------------
__global__ void k_zero() {
    int i = blockIdx.x * blockDim.x + threadIdx.x;
    if (i < NN) { g_deg[i] = 0; g_cursor[i] = 0; g_sea0[i] = 0.f; g_sea1[i] = 0.f; }
}

__global__ void k_count(const int* __restrict__ ei) {
    int e = blockIdx.x * blockDim.x + threadIdx.x;
    if (e < EE) atomicAdd(&g_deg[ei[EE + e]], 1);
}

// 1024 threads, 10 elems each (serial) + one shared scan
__global__ void k_scan() {
    __shared__ int sh[1024];
    int t = threadIdx.x;
    int loc[10];
    int tot = 0;
    #pragma unroll
    for (int j = 0; j < 10; j++) {
        int idx = t * 10 + j;
        int v = (idx < NN) ? g_deg[idx] : 0;
        loc[j] = tot;           // exclusive local prefix
        tot += v;
    }
    sh[t] = tot;
    __syncthreads();
    int sum = tot;
    #pragma unroll
    for (int s = 1; s < 1024; s <<= 1) {
        int u = (t >= s) ? sh[t - s] : 0;
        __syncthreads();
        sum += u;
        sh[t] = sum;
        __syncthreads();
    }
    int base = sum - tot;       // exclusive across threads
    #pragma unroll
    for (int j = 0; j < 10; j++) {
        int idx = t * 10 + j;
        if (idx < NN) g_off[idx] = base + loc[j];
    }
    if (t == 1023) g_off[NN] = sum;
}

__global__ void k_scatter(const int* __restrict__ ei, const float* __restrict__ ea) {
    int e = blockIdx.x * blockDim.x + threadIdx.x;
    if (e < EE) {
        int src = ei[e];
        int dst = ei[EE + e];
        int pos = g_off[dst] + atomicAdd(&g_cursor[dst], 1);
        g_slot[pos] = src;
        atomicAdd(&g_sea0[dst], ea[2 * e]);
        atomicAdd(&g_sea1[dst], ea[2 * e + 1]);
    }
}

// x -> gA_hi/gA_lo fp16 (padding rows zeroed)
__global__ void k_split_x(const float* __restrict__ h) {
    int i = blockIdx.x * blockDim.x + threadIdx.x;
    if (i < MPAD * CC) {
        float v = (i < NN * CC) ? h[i] : 0.0f;
        __half hi = __float2half_rn(v);
        __half lo = __float2half_rn(v - __half2float(hi));
        gA_hi[i] = hi;
        gA_lo[i] = lo;
    }
}

__global__ void k_prep_B(const float* __restrict__ nw, const float* __restrict__ ow) {
    int i = blockIdx.x * blockDim.x + threadIdx.x;
    if (i < LL * 512 * CC) {
        int l = i / (512 * CC);
        int r = i - l * 512 * CC;
        int n = r >> 8, k = r & 255;
        float v = (n < CC) ? nw[l * CC * CC + k * CC + n]
                           : ow[l * CC * CC + k * CC + (n - CC)];
        gB[i] = __float2half_rn(v);
    }
}

// ---------------- HMMA GEMM (fp16 2-pass, cp.async double-buffered) ----------------
#define SW128(x) ((x) ^ (((x) >> 3) & 0x70))

__device__ __forceinline__ uint32_t s2u(const void* p) {
    uint32_t a;
    asm("{ .reg .u64 t; cvta.to.shared.u64 t, %1; cvt.u32.u64 %0, t; }" : "=r"(a) : "l"(p));
    return a;
}

__device__ __forceinline__ void cpa16(uint32_t saddr, const void* gaddr) {
    asm volatile("cp.async.cg.shared.global [%0], [%1], 16;" :: "r"(saddr), "l"(gaddr));
}

__device__ __forceinline__ void ldsm_x4(uint32_t& r0, uint32_t& r1, uint32_t& r2, uint32_t& r3,
                                        uint32_t addr) {
    asm volatile("ldmatrix.sync.aligned.m8n8.x4.shared.b16 {%0,%1,%2,%3}, [%4];"
                 : "=r"(r0), "=r"(r1), "=r"(r2), "=r"(r3) : "r"(addr));
}

__device__ __forceinline__ void mma16816(float* c, const uint32_t* a, const uint32_t* b) {
    asm volatile(
        "mma.sync.aligned.m16n8k16.row.col.f32.f16.f16.f32 "
        "{%0,%1,%2,%3}, {%4,%5,%6,%7}, {%8,%9}, {%0,%1,%2,%3};"
        : "+f"(c[0]), "+f"(c[1]), "+f"(c[2]), "+f"(c[3])
        : "r"(a[0]), "r"(a[1]), "r"(a[2]), "r"(a[3]), "r"(b[0]), "r"(b[1]));
}

__device__ __forceinline__ uint32_t packbf2(float a, float b) {
    __nv_bfloat162 t = __float22bfloat162_rn(make_float2(a, b));
    return *reinterpret_cast<uint32_t*>(&t);
}

#define TB 16384                         // one tile buffer: 128 rows x 64 halves x 2B
#define STAGE (3 * TB)                   // Ahi, Alo, B
#define SMEM_TOTAL (2 * STAGE)           // 98304

__device__ __forceinline__ void load_chunk(uint32_t st, const __half* Bl,
                                           int m0, int nb, int kg, int tid) {
    uint32_t uAhi = st, uAlo = st + TB, uB = st + 2 * TB;
    #pragma unroll
    for (int it = 0; it < 4; it++) {
        int i = tid + it * 256;
        int r = i >> 3, c = i & 7;
        uint32_t so = SW128((uint32_t)(r * 128 + c * 16));
        int ga = (m0 + r) * CC + kg + c * 8;
        int gb = (nb * 128 + r) * CC + kg + c * 8;
        cpa16(uAhi + so, &gA_hi[ga]);
        cpa16(uAlo + so, &gA_lo[ga]);
        cpa16(uB + so, &Bl[gb]);
    }
}

// grid (79, 4): tile [bx*128, by*128] of [MPAD, 512]
__global__ __launch_bounds__(256) void k_gemm_tc(int layer) {
    extern __shared__ char smem[];
    uint32_t ubase = s2u(smem);
    const __half* Bl = gB + layer * 512 * CC;

    int tid = threadIdx.x, wid = tid >> 5, lid = tid & 31;
    int m0 = blockIdx.x * 128;
    int nblk = blockIdx.y;
    int warp_m = (wid & 3) * 32;
    int warp_n = (wid >> 2) * 64;

    float acc[2][8][4];
    #pragma unroll
    for (int t = 0; t < 2; t++)
        #pragma unroll
        for (int n = 0; n < 8; n++)
            #pragma unroll
            for (int j = 0; j < 4; j++) acc[t][n][j] = 0.f;

    int g = lid >> 3, rid = lid & 7;

    // preload chunk 0
    load_chunk(ubase, Bl, m0, nblk, 0, tid);
    asm volatile("cp.async.commit_group;");

    for (int ch = 0; ch < 4; ch++) {
        if (ch < 3) {
            load_chunk(ubase + ((ch + 1) & 1) * STAGE, Bl, m0, nblk, (ch + 1) * 64, tid);
            asm volatile("cp.async.commit_group;");
            asm volatile("cp.async.wait_group 1;");
        } else {
            asm volatile("cp.async.wait_group 0;");
        }
        __syncthreads();

        uint32_t st = ubase + (ch & 1) * STAGE;
        uint32_t uAhi = st, uAlo = st + TB, uB = st + 2 * TB;

        #pragma unroll
        for (int ks = 0; ks < 4; ks++) {
            int kc2 = ks * 2;
            // B fragments (shared by both passes)
            uint32_t b[8][2];
            #pragma unroll
            for (int p = 0; p < 4; p++) {
                int row = warp_n + p * 16 + ((g >> 1) ? 8 : 0) + rid;
                int chunk = kc2 + (g & 1);
                ldsm_x4(b[2 * p][0], b[2 * p][1], b[2 * p + 1][0], b[2 * p + 1][1],
                        uB + SW128((uint32_t)(row * 128 + chunk * 16)));
            }
            // A_hi / A_lo fragments
            uint32_t ah[2][4], al[2][4];
            #pragma unroll
            for (int t = 0; t < 2; t++) {
                int row = warp_m + t * 16 + ((g & 1) ? 8 : 0) + rid;
                int chunk = kc2 + (g >> 1);
                uint32_t so = SW128((uint32_t)(row * 128 + chunk * 16));
                ldsm_x4(ah[t][0], ah[t][1], ah[t][2], ah[t][3], uAhi + so);
                ldsm_x4(al[t][0], al[t][1], al[t][2], al[t][3], uAlo + so);
            }
            #pragma unroll
            for (int t = 0; t < 2; t++)
                #pragma unroll
                for (int n = 0; n < 8; n++)
                    mma16816(acc[t][n], ah[t], b[n]);
            #pragma unroll
            for (int t = 0; t < 2; t++)
                #pragma unroll
                for (int n = 0; n < 8; n++)
                    mma16816(acc[t][n], al[t], b[n]);
        }
        __syncthreads();
    }

    int qm = lid >> 2, qn = (lid & 3) * 2;
    #pragma unroll
    for (int t = 0; t < 2; t++) {
        #pragma unroll
        for (int n = 0; n < 8; n++) {
            int row0 = m0 + warp_m + t * 16 + qm;
            int colg = nblk * 128 + warp_n + n * 8 + qn;
            if (colg < 256) {
                if (row0 < NN)
                    g_hnb[row0 * 128 + (colg >> 1)] = packbf2(acc[t][n][0], acc[t][n][1]);
                if (row0 + 8 < NN)
                    g_hnb[(row0 + 8) * 128 + (colg >> 1)] = packbf2(acc[t][n][2], acc[t][n][3]);
            } else {
                int col = colg - 256;
                if (row0 < NN)
                    *(float2*)&g_hw[row0 * CC + col] = make_float2(acc[t][n][0], acc[t][n][1]);
                if (row0 + 8 < NN)
                    *(float2*)&g_hw[(row0 + 8) * CC + col] = make_float2(acc[t][n][2], acc[t][n][3]);
            }
        }
    }
}

// ---------------- warp-per-node aggregation + KAF + split for next layer ----------------
__device__ __forceinline__ void add8(float* acc, uint4 v) {
    uint32_t w[4] = {v.x, v.y, v.z, v.w};
    #pragma unroll
    for (int u = 0; u < 4; u++) {
        acc[2 * u]     += __uint_as_float(w[u] << 16);
        acc[2 * u + 1] += __uint_as_float(w[u] & 0xFFFF0000u);
    }
}

__global__ __launch_bounds__(256) void k_aggr_kaf(const float* __restrict__ ew,
                                                  const float* __restrict__ bias,
                                                  const float* __restrict__ alpha,
                                                  float* __restrict__ out, int last) {
    int n = blockIdx.x * 8 + (threadIdx.x >> 5);
    if (n >= NN) return;
    int lane = threadIdx.x & 31;
    int o0 = g_off[n], o1 = g_off[n + 1];
    int deg = o1 - o0;
    int col = lane * 4;

    float acc[8];
    #pragma unroll
    for (int k = 0; k < 8; k++) acc[k] = 0.f;

    int e = o0;
    for (; e + 4 <= o1; e += 4) {
        int s0 = g_slot[e], s1 = g_slot[e + 1], s2 = g_slot[e + 2], s3 = g_slot[e + 3];
        uint4 v0 = *(const uint4*)&g_hnb[s0 * 128 + col];
        uint4 v1 = *(const uint4*)&g_hnb[s1 * 128 + col];
        uint4 v2 = *(const uint4*)&g_hnb[s2 * 128 + col];
        uint4 v3 = *(const uint4*)&g_hnb[s3 * 128 + col];
        add8(acc, v0); add8(acc, v1); add8(acc, v2); add8(acc, v3);
    }
    for (; e < o1; e++) {
        int s = g_slot[e];
        uint4 v = *(const uint4*)&g_hnb[s * 128 + col];
        add8(acc, v);
    }

    float inv = (deg > 0) ? 1.0f / (float)deg : 0.0f;
    float sea0 = g_sea0[n] * inv, sea1 = g_sea1[n] * inv;

    int ch0 = lane * 8;
    float4 hwa = *(const float4*)&g_hw[n * CC + ch0];
    float4 hwb = *(const float4*)&g_hw[n * CC + ch0 + 4];
    float hw[8] = {hwa.x, hwa.y, hwa.z, hwa.w, hwb.x, hwb.y, hwb.z, hwb.w};

    float res[8];
    #pragma unroll
    for (int k = 0; k < 8; k++) {
        int c = ch0 + k;
        float s = acc[k] * inv + sea0 * ew[c] + sea1 * ew[CC + c] + hw[k] + bias[c];
        float u0 = s + 4.0f;
        float K = __expf(-GAMMA * u0 * u0);
        float r = __expf(KAF_C1 * u0 - 0.125f);
        const float4* ap = (const float4*)&alpha[c * DD];
        float t = 0.f;
        #pragma unroll
        for (int v5 = 0; v5 < 5; v5++) {
            float4 a4 = ap[v5];
            t += a4.x * K; K *= r; r *= KAF_Q;
            t += a4.y * K; K *= r; r *= KAF_Q;
            t += a4.z * K; K *= r; r *= KAF_Q;
            t += a4.w * K; K *= r; r *= KAF_Q;
        }
        res[k] = t;
    }

    if (last) {
        *(float4*)&out[n * CC + ch0]     = make_float4(res[0], res[1], res[2], res[3]);
        *(float4*)&out[n * CC + ch0 + 4] = make_float4(res[4], res[5], res[6], res[7]);
    } else {
        uint32_t hi[4], lo[4];
        #pragma unroll
        for (int u = 0; u < 4; u++) {
            __half h0 = __float2half_rn(res[2 * u]);
            __half h1 = __float2half_rn(res[2 * u + 1]);
            __half l0 = __float2half_rn(res[2 * u] - __half2float(h0));
            __half l1 = __float2half_rn(res[2 * u + 1] - __half2float(h1));
            hi[u] = ((uint32_t)*(uint16_t*)&h1 << 16) | *(uint16_t*)&h0;
            lo[u] = ((uint32_t)*(uint16_t*)&l1 << 16) | *(uint16_t*)&l0;
        }
        *(uint4*)&gA_hi[n * CC + ch0] = make_uint4(hi[0], hi[1], hi[2], hi[3]);
        *(uint4*)&gA_lo[n * CC + ch0] = make_uint4(lo[0], lo[1], lo[2], lo[3]);
    }
}

// ---------------- launch ----------------
static cudaStream_t g_s2 = nullptr;
static cudaEvent_t g_evF = nullptr, g_evJ = nullptr;

extern "C" void kernel_launch(void* const* d_in, const int* in_sizes, int n_in,
                              void* d_out, int out_size) {
    const float* x       = (const float*)d_in[0];
    const int*   ei      = (const int*)d_in[1];
    const float* ea      = (const float*)d_in[2];
    const float* node_w  = (const float*)d_in[3];
    const float* edge_w  = (const float*)d_in[4];
    const float* neigh_w = (const float*)d_in[5];
    const float* bias    = (const float*)d_in[6];
    const float* alpha   = (const float*)d_in[7];
    float* out = (float*)d_out;

    if (!g_s2) {   // first call is the (uncaptured) correctness run
        cudaStreamCreateWithFlags(&g_s2, cudaStreamNonBlocking);
        cudaEventCreateWithFlags(&g_evF, cudaEventDisableTiming);
        cudaEventCreateWithFlags(&g_evJ, cudaEventDisableTiming);
        cudaFuncSetAttribute(k_gemm_tc, cudaFuncAttributeMaxDynamicSharedMemorySize, SMEM_TOTAL);
    }

    // fork: CSR chain on side stream
    cudaEventRecord(g_evF, 0);
    cudaStreamWaitEvent(g_s2, g_evF, 0);
    k_zero<<<(NN + 255) / 256, 256, 0, g_s2>>>();
    k_count<<<(EE + 255) / 256, 256, 0, g_s2>>>(ei);
    k_scan<<<1, 1024, 0, g_s2>>>();
    k_scatter<<<(EE + 255) / 256, 256, 0, g_s2>>>(ei, ea);
    cudaEventRecord(g_evJ, g_s2);

    // main: dense prep + layer-0 GEMM (independent of CSR)
    k_split_x<<<(MPAD * CC + 255) / 256, 256>>>(x);
    k_prep_B<<<(LL * 512 * CC + 255) / 256, 256>>>(neigh_w, node_w);

    dim3 gg(NT, 4);
    k_gemm_tc<<<gg, 256, SMEM_TOTAL>>>(0);
    cudaStreamWaitEvent(0, g_evJ, 0);   // join before aggregation needs CSR

    for (int l = 0; l < LL; l++) {
        if (l > 0) k_gemm_tc<<<gg, 256, SMEM_TOTAL>>>(l);
        k_aggr_kaf<<<NN / 8, 256>>>(edge_w + l * 2 * CC, bias + l * CC,
                                    alpha + l * CC * DD, out, (l == LL - 1) ? 1 : 0);
    }
}

// round 7
// speedup vs baseline: 1.7177x; 1.3845x over previous
#include <cuda_runtime.h>
#include <cuda_fp16.h>
#include <cstdint>

#define NN 10000
#define MPAD 10112        // 79 * 128
#define NT 79
#define EE 320000
#define CC 256
#define KK 512            // GEMM K dim: [agg | h]
#define LL 3
#define DD 20
#define GAMMA 0.705078125f       // 0.125 / interval^2, interval = 8/19
#define KAF_C1 0.59375f          // 2*gamma*interval
#define KAF_Q  0.778800783f      // exp(-0.25)

// ---------------- scratch (device globals) ----------------
__device__ int   g_deg[NN];
__device__ int   g_off[NN + 1];
__device__ int   g_cursor[NN];
__device__ int   g_slot[EE];
__device__ float g_sea0[NN];
__device__ float g_sea1[NN];
__device__ float g_inv[NN];
__device__ float g_sc0[NN];
__device__ float g_sc1[NN];
// Ping-pong A matrices. Row layout [KK]: cols 0..255 = agg, cols 256..511 = h
__device__ __align__(16) __half gA_hi0[MPAD * KK];
__device__ __align__(16) __half gA_lo0[MPAD * KK];
__device__ __align__(16) __half gA_hi1[MPAD * KK];
__device__ __align__(16) __half gA_lo1[MPAD * KK];
// B [l][n_out(256)][k(512)]: k<256 -> neigh_w[k][n], k>=256 -> node_w[k-256][n]
__device__ __align__(16) __half gB[LL * CC * KK];

// ---------------- setup kernels ----------------
__global__ void k_zero() {
    int i = blockIdx.x * blockDim.x + threadIdx.x;
    if (i < NN) { g_deg[i] = 0; g_cursor[i] = 0; g_sea0[i] = 0.f; g_sea1[i] = 0.f; }
}

__global__ void k_count(const int* __restrict__ ei) {
    int e = blockIdx.x * blockDim.x + threadIdx.x;
    if (e < EE) atomicAdd(&g_deg[ei[EE + e]], 1);
}

__global__ void k_scan() {
    __shared__ int sh[1024];
    int t = threadIdx.x;
    int loc[10];
    int tot = 0;
    #pragma unroll
    for (int j = 0; j < 10; j++) {
        int idx = t * 10 + j;
        int v = (idx < NN) ? g_deg[idx] : 0;
        loc[j] = tot;
        tot += v;
    }
    sh[t] = tot;
    __syncthreads();
    int sum = tot;
    #pragma unroll
    for (int s = 1; s < 1024; s <<= 1) {
        int u = (t >= s) ? sh[t - s] : 0;
        __syncthreads();
        sum += u;
        sh[t] = sum;
        __syncthreads();
    }
    int base = sum - tot;
    #pragma unroll
    for (int j = 0; j < 10; j++) {
        int idx = t * 10 + j;
        if (idx < NN) g_off[idx] = base + loc[j];
    }
    if (t == 1023) g_off[NN] = sum;
}

__global__ void k_scatter(const int* __restrict__ ei, const float* __restrict__ ea) {
    int e = blockIdx.x * blockDim.x + threadIdx.x;
    if (e < EE) {
        int src = ei[e];
        int dst = ei[EE + e];
        int pos = g_off[dst] + atomicAdd(&g_cursor[dst], 1);
        g_slot[pos] = src;
        atomicAdd(&g_sea0[dst], ea[2 * e]);
        atomicAdd(&g_sea1[dst], ea[2 * e + 1]);
    }
}

__global__ void k_post() {
    int i = blockIdx.x * blockDim.x + threadIdx.x;
    if (i < NN) {
        int d = g_deg[i];
        float inv = (d > 0) ? 1.0f / (float)d : 0.0f;
        g_inv[i] = inv;
        g_sc0[i] = g_sea0[i] * inv;
        g_sc1[i] = g_sea1[i] * inv;
    }
}

// x -> h part (cols 256..511) of A buffer 0, fp16 hi/lo
__global__ void k_split_x(const float* __restrict__ x) {
    int i = blockIdx.x * blockDim.x + threadIdx.x;
    if (i < NN * CC) {
        int row = i >> 8, col = i & 255;
        float v = x[i];
        __half hi = __float2half_rn(v);
        __half lo = __float2half_rn(v - __half2float(hi));
        gA_hi0[row * KK + 256 + col] = hi;
        gA_lo0[row * KK + 256 + col] = lo;
    }
}

__global__ void k_prep_B(const float* __restrict__ nw, const float* __restrict__ ow) {
    int i = blockIdx.x * blockDim.x + threadIdx.x;
    if (i < LL * CC * KK) {
        int l = i / (CC * KK);
        int r = i - l * CC * KK;
        int n = r >> 9, k = r & 511;
        float v = (k < 256) ? nw[l * CC * CC + k * CC + n]
                            : ow[l * CC * CC + (k - 256) * CC + n];
        gB[i] = __float2half_rn(v);
    }
}

// ---------------- gather: agg[n] = inv * sum h[src] (fp16 in, fp32 acc) ----------------
__device__ __forceinline__ void addh8(float* acc, uint4 v) {
    uint32_t w[4] = {v.x, v.y, v.z, v.w};
    #pragma unroll
    for (int u = 0; u < 4; u++) {
        __half2 h = *reinterpret_cast<__half2*>(&w[u]);
        float2 f = __half22float2(h);
        acc[2 * u] += f.x;
        acc[2 * u + 1] += f.y;
    }
}

// reads h half of buffer `hi`, writes agg half of same buffer (hi + lo split)
__global__ __launch_bounds__(256) void k_gather(const __half* __restrict__ Ahi,
                                                __half* __restrict__ AhiW,
                                                __half* __restrict__ AloW) {
    int n = blockIdx.x * 8 + (threadIdx.x >> 5);
    if (n >= NN) return;
    int lane = threadIdx.x & 31;
    int o0 = g_off[n], o1 = g_off[n + 1];
    int col4 = lane * 4;
    const uint32_t* hv = (const uint32_t*)Ahi;

    float acc[8];
    #pragma unroll
    for (int k = 0; k < 8; k++) acc[k] = 0.f;

    int e = o0;
    for (; e + 8 <= o1; e += 8) {
        int s[8];
        #pragma unroll
        for (int j = 0; j < 8; j++) s[j] = g_slot[e + j];
        uint4 v[8];
        #pragma unroll
        for (int j = 0; j < 8; j++) v[j] = *(const uint4*)&hv[s[j] * 256 + 128 + col4];
        #pragma unroll
        for (int j = 0; j < 8; j++) addh8(acc, v[j]);
    }
    for (; e < o1; e++) {
        int s = g_slot[e];
        addh8(acc, *(const uint4*)&hv[s * 256 + 128 + col4]);
    }

    float inv = g_inv[n];
    uint32_t hi[4], lo[4];
    #pragma unroll
    for (int u = 0; u < 4; u++) {
        float a0 = acc[2 * u] * inv, a1 = acc[2 * u + 1] * inv;
        __half h0 = __float2half_rn(a0), h1 = __float2half_rn(a1);
        __half l0 = __float2half_rn(a0 - __half2float(h0));
        __half l1 = __float2half_rn(a1 - __half2float(h1));
        hi[u] = ((uint32_t)*(uint16_t*)&h1 << 16) | *(uint16_t*)&h0;
        lo[u] = ((uint32_t)*(uint16_t*)&l1 << 16) | *(uint16_t*)&l0;
    }
    *(uint4*)&((uint32_t*)AhiW)[n * 256 + col4] = make_uint4(hi[0], hi[1], hi[2], hi[3]);
    *(uint4*)&((uint32_t*)AloW)[n * 256 + col4] = make_uint4(lo[0], lo[1], lo[2], lo[3]);
}

// ---------------- fused GEMM + rank2 + bias + KAF ----------------
#define SW128(x) ((x) ^ (((x) >> 3) & 0x70))

__device__ __forceinline__ uint32_t s2u(const void* p) {
    uint32_t a;
    asm("{ .reg .u64 t; cvta.to.shared.u64 t, %1; cvt.u32.u64 %0, t; }" : "=r"(a) : "l"(p));
    return a;
}

__device__ __forceinline__ void cpa16(uint32_t saddr, const void* gaddr) {
    asm volatile("cp.async.cg.shared.global [%0], [%1], 16;" :: "r"(saddr), "l"(gaddr));
}

__device__ __forceinline__ void ldsm_x4(uint32_t& r0, uint32_t& r1, uint32_t& r2, uint32_t& r3,
                                        uint32_t addr) {
    asm volatile("ldmatrix.sync.aligned.m8n8.x4.shared.b16 {%0,%1,%2,%3}, [%4];"
                 : "=r"(r0), "=r"(r1), "=r"(r2), "=r"(r3) : "r"(addr));
}

__device__ __forceinline__ void mma16816(float* c, const uint32_t* a, const uint32_t* b) {
    asm volatile(
        "mma.sync.aligned.m16n8k16.row.col.f32.f16.f16.f32 "
        "{%0,%1,%2,%3}, {%4,%5,%6,%7}, {%8,%9}, {%0,%1,%2,%3};"
        : "+f"(c[0]), "+f"(c[1]), "+f"(c[2]), "+f"(c[3])
        : "r"(a[0]), "r"(a[1]), "r"(a[2]), "r"(a[3]), "r"(b[0]), "r"(b[1]));
}

__device__ __forceinline__ float kaf_eval(float s, const float* a) {
    float u = s + 4.0f;
    float K = __expf(-GAMMA * u * u);
    float r = __expf(KAF_C1 * u - 0.125f);
    float t = 0.f;
    #pragma unroll
    for (int d = 0; d < DD; d++) { t += a[d] * K; K *= r; r *= KAF_Q; }
    return t;
}

#define TB 16384                         // 128 rows x 64 halves x 2B
#define STAGE (3 * TB)                   // Ahi, Alo, B
#define SMEM_TOTAL (2 * STAGE)           // 98304

__device__ __forceinline__ void load_chunk(uint32_t st,
                                           const __half* Ahi, const __half* Alo,
                                           const __half* Bl,
                                           int m0, int nb, int kg, int tid) {
    uint32_t uAhi = st, uAlo = st + TB, uB = st + 2 * TB;
    #pragma unroll
    for (int it = 0; it < 4; it++) {
        int i = tid + it * 256;
        int r = i >> 3, c = i & 7;
        uint32_t so = SW128((uint32_t)(r * 128 + c * 16));
        int ga = (m0 + r) * KK + kg + c * 8;
        int gb = (nb * 128 + r) * KK + kg + c * 8;
        cpa16(uAhi + so, &Ahi[ga]);
        cpa16(uAlo + so, &Alo[ga]);
        cpa16(uB + so, &Bl[gb]);
    }
}

// grid (79, 2): tile rows bx*128, output cols by*128. K=512 in 8 chunks.
// reads A from (Ahi, Alo); writes next-layer h into (AhiN, AloN) -- DIFFERENT buffer
__global__ __launch_bounds__(256) void k_gemm_fused(int layer,
                                                    const __half* __restrict__ Ahi,
                                                    const __half* __restrict__ Alo,
                                                    __half* __restrict__ AhiN,
                                                    __half* __restrict__ AloN,
                                                    const float* __restrict__ ew,
                                                    const float* __restrict__ bias,
                                                    const float* __restrict__ alpha,
                                                    float* __restrict__ out, int last) {
    extern __shared__ char smem[];
    uint32_t ubase = s2u(smem);
    const __half* Bl = gB + layer * CC * KK;

    int tid = threadIdx.x, wid = tid >> 5, lid = tid & 31;
    int m0 = blockIdx.x * 128;
    int nblk = blockIdx.y;
    int c0 = nblk * 128;
    int warp_m = (wid & 3) * 32;
    int warp_n = (wid >> 2) * 64;

    float acc[2][8][4];
    #pragma unroll
    for (int t = 0; t < 2; t++)
        #pragma unroll
        for (int n = 0; n < 8; n++)
            #pragma unroll
            for (int j = 0; j < 4; j++) acc[t][n][j] = 0.f;

    int g = lid >> 3, rid = lid & 7;

    load_chunk(ubase, Ahi, Alo, Bl, m0, nblk, 0, tid);
    asm volatile("cp.async.commit_group;");

    for (int ch = 0; ch < 8; ch++) {
        if (ch < 7) {
            load_chunk(ubase + ((ch + 1) & 1) * STAGE, Ahi, Alo, Bl, m0, nblk, (ch + 1) * 64, tid);
            asm volatile("cp.async.commit_group;");
            asm volatile("cp.async.wait_group 1;");
        } else {
            asm volatile("cp.async.wait_group 0;");
        }
        __syncthreads();

        uint32_t st = ubase + (ch & 1) * STAGE;
        uint32_t uAhi = st, uAlo = st + TB, uB = st + 2 * TB;

        #pragma unroll
        for (int ks = 0; ks < 4; ks++) {
            int kc2 = ks * 2;
            uint32_t b[8][2];
            #pragma unroll
            for (int p = 0; p < 4; p++) {
                int row = warp_n + p * 16 + ((g >> 1) ? 8 : 0) + rid;
                int chunk = kc2 + (g & 1);
                ldsm_x4(b[2 * p][0], b[2 * p][1], b[2 * p + 1][0], b[2 * p + 1][1],
                        uB + SW128((uint32_t)(row * 128 + chunk * 16)));
            }
            uint32_t ah[2][4], al[2][4];
            #pragma unroll
            for (int t = 0; t < 2; t++) {
                int row = warp_m + t * 16 + ((g & 1) ? 8 : 0) + rid;
                int chunk = kc2 + (g >> 1);
                uint32_t so = SW128((uint32_t)(row * 128 + chunk * 16));
                ldsm_x4(ah[t][0], ah[t][1], ah[t][2], ah[t][3], uAhi + so);
                ldsm_x4(al[t][0], al[t][1], al[t][2], al[t][3], uAlo + so);
            }
            #pragma unroll
            for (int t = 0; t < 2; t++)
                #pragma unroll
                for (int n = 0; n < 8; n++)
                    mma16816(acc[t][n], ah[t], b[n]);
            #pragma unroll
            for (int t = 0; t < 2; t++)
                #pragma unroll
                for (int n = 0; n < 8; n++)
                    mma16816(acc[t][n], al[t], b[n]);
        }
        __syncthreads();
    }

    // stage per-column params: ew0[128] ew1[128] bias[128] alpha[128*20]
    float* sP = (float*)smem;
    for (int i = tid; i < 128; i += 256) {
        int c = c0 + i;
        sP[i] = ew[c];
        sP[128 + i] = ew[CC + c];
        sP[256 + i] = bias[c];
    }
    for (int i = tid; i < 128 * DD; i += 256)
        sP[384 + i] = alpha[c0 * DD + i];
    __syncthreads();

    int qm = lid >> 2, qn = (lid & 3) * 2;
    uint32_t* ghi = (uint32_t*)AhiN;
    uint32_t* glo = (uint32_t*)AloN;
    #pragma unroll
    for (int t = 0; t < 2; t++) {
        #pragma unroll
        for (int rr = 0; rr < 2; rr++) {
            int row = m0 + warp_m + t * 16 + qm + rr * 8;
            if (row >= NN) continue;
            float sc0 = g_sc0[row], sc1 = g_sc1[row];
            #pragma unroll
            for (int n = 0; n < 8; n++) {
                int lc = warp_n + n * 8 + qn;
                float s0 = acc[t][n][rr * 2]     + sc0 * sP[lc]     + sc1 * sP[128 + lc]     + sP[256 + lc];
                float s1 = acc[t][n][rr * 2 + 1] + sc0 * sP[lc + 1] + sc1 * sP[128 + lc + 1] + sP[256 + lc + 1];
                float r0 = kaf_eval(s0, &sP[384 + lc * DD]);
                float r1 = kaf_eval(s1, &sP[384 + (lc + 1) * DD]);
                if (last) {
                    *(float2*)&out[row * CC + c0 + lc] = make_float2(r0, r1);
                } else {
                    __half h0 = __float2half_rn(r0), h1 = __float2half_rn(r1);
                    __half l0 = __float2half_rn(r0 - __half2float(h0));
                    __half l1 = __float2half_rn(r1 - __half2float(h1));
                    uint32_t phi = ((uint32_t)*(uint16_t*)&h1 << 16) | *(uint16_t*)&h0;
                    uint32_t plo = ((uint32_t)*(uint16_t*)&l1 << 16) | *(uint16_t*)&l0;
                    int idx = row * 256 + 128 + ((c0 + lc) >> 1);
                    ghi[idx] = phi;
                    glo[idx] = plo;
                }
            }
        }
    }
}

// ---------------- launch ----------------
static cudaStream_t g_s2 = nullptr;
static cudaEvent_t g_evF = nullptr, g_evJ = nullptr;

extern "C" void kernel_launch(void* const* d_in, const int* in_sizes, int n_in,
                              void* d_out, int out_size) {
    const float* x       = (const float*)d_in[0];
    const int*   ei      = (const int*)d_in[1];
    const float* ea      = (const float*)d_in[2];
    const float* node_w  = (const float*)d_in[3];
    const float* edge_w  = (const float*)d_in[4];
    const float* neigh_w = (const float*)d_in[5];
    const float* bias    = (const float*)d_in[6];
    const float* alpha   = (const float*)d_in[7];
    float* out = (float*)d_out;

    if (!g_s2) {
        cudaStreamCreateWithFlags(&g_s2, cudaStreamNonBlocking);
        cudaEventCreateWithFlags(&g_evF, cudaEventDisableTiming);
        cudaEventCreateWithFlags(&g_evJ, cudaEventDisableTiming);
        cudaFuncSetAttribute(k_gemm_fused, cudaFuncAttributeMaxDynamicSharedMemorySize, SMEM_TOTAL);
    }

    __half *hi0, *lo0, *hi1, *lo1;
    cudaGetSymbolAddress((void**)&hi0, gA_hi0);
    cudaGetSymbolAddress((void**)&lo0, gA_lo0);
    cudaGetSymbolAddress((void**)&hi1, gA_hi1);
    cudaGetSymbolAddress((void**)&lo1, gA_lo1);
    __half* HI[2] = {hi0, hi1};
    __half* LO[2] = {lo0, lo1};

    // fork: CSR chain on side stream
    cudaEventRecord(g_evF, 0);
    cudaStreamWaitEvent(g_s2, g_evF, 0);
    k_zero<<<(NN + 255) / 256, 256, 0, g_s2>>>();
    k_count<<<(EE + 255) / 256, 256, 0, g_s2>>>(ei);
    k_scan<<<1, 1024, 0, g_s2>>>();
    k_scatter<<<(EE + 255) / 256, 256, 0, g_s2>>>(ei, ea);
    k_post<<<(NN + 255) / 256, 256, 0, g_s2>>>();
    cudaEventRecord(g_evJ, g_s2);

    // main: dense prep
    k_split_x<<<(NN * CC + 255) / 256, 256>>>(x);
    k_prep_B<<<(LL * CC * KK + 255) / 256, 256>>>(neigh_w, node_w);
    cudaStreamWaitEvent(0, g_evJ, 0);

    dim3 gg(NT, 2);
    for (int l = 0; l < LL; l++) {
        int b = l & 1;
        k_gather<<<(NN + 7) / 8, 256>>>(HI[b], HI[b], LO[b]);
        k_gemm_fused<<<gg, 256, SMEM_TOTAL>>>(l, HI[b], LO[b], HI[b ^ 1], LO[b ^ 1],
                                              edge_w + l * 2 * CC, bias + l * CC,
                                              alpha + l * CC * DD, out, (l == LL - 1) ? 1 : 0);
    }
}

// round 8
// speedup vs baseline: 1.9216x; 1.1186x over previous
#include <cuda_runtime.h>
#include <cuda_fp16.h>
#include <cstdint>

#define NN 10000
#define MPAD 10112        // 79 * 128
#define NT 79
#define EE 320000
#define CC 256
#define KK 512            // GEMM K dim: [agg | h]
#define LL 3
#define DD 20
#define GAMMA 0.705078125f       // 0.125 / interval^2, interval = 8/19
#define KAF_C1 0.59375f          // 2*gamma*interval
#define KAF_Q  0.778800783f      // exp(-0.25)

// ---------------- scratch (device globals) ----------------
__device__ int   g_deg[NN];
__device__ int   g_off[NN + 1];
__device__ int   g_cursor[NN];
__device__ int   g_slot[EE];
__device__ float g_sea0[NN];
__device__ float g_sea1[NN];
__device__ float g_inv[NN];
__device__ float g_sc0[NN];
__device__ float g_sc1[NN];
// Ping-pong A matrices (single fp16). Row layout [KK]: cols 0..255 = agg, cols 256..511 = h
__device__ __align__(16) __half gA0[MPAD * KK];
__device__ __align__(16) __half gA1[MPAD * KK];
// B [l][n_out(256)][k(512)]: k<256 -> neigh_w[k][n], k>=256 -> node_w[k-256][n]
__device__ __align__(16) __half gB[LL * CC * KK];

// ---------------- setup kernels ----------------
__global__ void k_zero() {
    int i = blockIdx.x * blockDim.x + threadIdx.x;
    if (i < NN) { g_deg[i] = 0; g_cursor[i] = 0; g_sea0[i] = 0.f; g_sea1[i] = 0.f; }
}

// count + edge-attr sums in one edge pass
__global__ void k_count(const int* __restrict__ ei, const float* __restrict__ ea) {
    int e = blockIdx.x * blockDim.x + threadIdx.x;
    if (e < EE) {
        int dst = ei[EE + e];
        atomicAdd(&g_deg[dst], 1);
        atomicAdd(&g_sea0[dst], ea[2 * e]);
        atomicAdd(&g_sea1[dst], ea[2 * e + 1]);
    }
}

// scan + post (inv, sc0, sc1) fused
__global__ void k_scan() {
    __shared__ int sh[1024];
    int t = threadIdx.x;
    int loc[10], dv[10];
    int tot = 0;
    #pragma unroll
    for (int j = 0; j < 10; j++) {
        int idx = t * 10 + j;
        int v = (idx < NN) ? g_deg[idx] : 0;
        dv[j] = v;
        loc[j] = tot;
        tot += v;
    }
    sh[t] = tot;
    __syncthreads();
    int sum = tot;
    #pragma unroll
    for (int s = 1; s < 1024; s <<= 1) {
        int u = (t >= s) ? sh[t - s] : 0;
        __syncthreads();
        sum += u;
        sh[t] = sum;
        __syncthreads();
    }
    int base = sum - tot;
    #pragma unroll
    for (int j = 0; j < 10; j++) {
        int idx = t * 10 + j;
        if (idx < NN) {
            g_off[idx] = base + loc[j];
            float inv = (dv[j] > 0) ? 1.0f / (float)dv[j] : 0.0f;
            g_inv[idx] = inv;
            g_sc0[idx] = g_sea0[idx] * inv;
            g_sc1[idx] = g_sea1[idx] * inv;
        }
    }
    if (t == 1023) g_off[NN] = sum;
}

__global__ void k_scatter(const int* __restrict__ ei) {
    int e = blockIdx.x * blockDim.x + threadIdx.x;
    if (e < EE) {
        int src = ei[e];
        int dst = ei[EE + e];
        int pos = g_off[dst] + atomicAdd(&g_cursor[dst], 1);
        g_slot[pos] = src;
    }
}

// x -> h part (cols 256..511) of A buffer 0
__global__ void k_split_x(const float* __restrict__ x) {
    int i = blockIdx.x * blockDim.x + threadIdx.x;
    if (i < NN * CC) {
        int row = i >> 8, col = i & 255;
        gA0[row * KK + 256 + col] = __float2half_rn(x[i]);
    }
}

__global__ void k_prep_B(const float* __restrict__ nw, const float* __restrict__ ow) {
    int i = blockIdx.x * blockDim.x + threadIdx.x;
    if (i < LL * CC * KK) {
        int l = i / (CC * KK);
        int r = i - l * CC * KK;
        int n = r >> 9, k = r & 511;
        float v = (k < 256) ? nw[l * CC * CC + k * CC + n]
                            : ow[l * CC * CC + (k - 256) * CC + n];
        gB[i] = __float2half_rn(v);
    }
}

// ---------------- gather: agg[n] = inv * sum h[src] (fp16 in, fp32 acc) ----------------
__device__ __forceinline__ void addh8(float* acc, uint4 v) {
    uint32_t w[4] = {v.x, v.y, v.z, v.w};
    #pragma unroll
    for (int u = 0; u < 4; u++) {
        __half2 h = *reinterpret_cast<__half2*>(&w[u]);
        float2 f = __half22float2(h);
        acc[2 * u] += f.x;
        acc[2 * u + 1] += f.y;
    }
}

__global__ __launch_bounds__(256) void k_gather(const __half* __restrict__ A,
                                                __half* __restrict__ AW) {
    int n = blockIdx.x * 8 + (threadIdx.x >> 5);
    if (n >= NN) return;
    int lane = threadIdx.x & 31;
    int o0 = g_off[n], o1 = g_off[n + 1];
    int col4 = lane * 4;
    const uint32_t* hv = (const uint32_t*)A;

    float acc[8];
    #pragma unroll
    for (int k = 0; k < 8; k++) acc[k] = 0.f;

    int e = o0;
    for (; e + 8 <= o1; e += 8) {
        int s[8];
        #pragma unroll
        for (int j = 0; j < 8; j++) s[j] = g_slot[e + j];
        uint4 v[8];
        #pragma unroll
        for (int j = 0; j < 8; j++) v[j] = *(const uint4*)&hv[s[j] * 256 + 128 + col4];
        #pragma unroll
        for (int j = 0; j < 8; j++) addh8(acc, v[j]);
    }
    for (; e < o1; e++) {
        int s = g_slot[e];
        addh8(acc, *(const uint4*)&hv[s * 256 + 128 + col4]);
    }

    float inv = g_inv[n];
    uint32_t pk[4];
    #pragma unroll
    for (int u = 0; u < 4; u++) {
        __half h0 = __float2half_rn(acc[2 * u] * inv);
        __half h1 = __float2half_rn(acc[2 * u + 1] * inv);
        pk[u] = ((uint32_t)*(uint16_t*)&h1 << 16) | *(uint16_t*)&h0;
    }
    *(uint4*)&((uint32_t*)AW)[n * 256 + col4] = make_uint4(pk[0], pk[1], pk[2], pk[3]);
}

// ---------------- fused GEMM + rank2 + bias + KAF ----------------
#define SW128(x) ((x) ^ (((x) >> 3) & 0x70))

__device__ __forceinline__ uint32_t s2u(const void* p) {
    uint32_t a;
    asm("{ .reg .u64 t; cvta.to.shared.u64 t, %1; cvt.u32.u64 %0, t; }" : "=r"(a) : "l"(p));
    return a;
}

__device__ __forceinline__ void cpa16(uint32_t saddr, const void* gaddr) {
    asm volatile("cp.async.cg.shared.global [%0], [%1], 16;" :: "r"(saddr), "l"(gaddr));
}

__device__ __forceinline__ void ldsm_x4(uint32_t& r0, uint32_t& r1, uint32_t& r2, uint32_t& r3,
                                        uint32_t addr) {
    asm volatile("ldmatrix.sync.aligned.m8n8.x4.shared.b16 {%0,%1,%2,%3}, [%4];"
                 : "=r"(r0), "=r"(r1), "=r"(r2), "=r"(r3) : "r"(addr));
}

__device__ __forceinline__ void mma16816(float* c, const uint32_t* a, const uint32_t* b) {
    asm volatile(
        "mma.sync.aligned.m16n8k16.row.col.f32.f16.f16.f32 "
        "{%0,%1,%2,%3}, {%4,%5,%6,%7}, {%8,%9}, {%0,%1,%2,%3};"
        : "+f"(c[0]), "+f"(c[1]), "+f"(c[2]), "+f"(c[3])
        : "r"(a[0]), "r"(a[1]), "r"(a[2]), "r"(a[3]), "r"(b[0]), "r"(b[1]));
}

__device__ __forceinline__ float kaf_eval(float s, const float* a) {
    float u = s + 4.0f;
    float K = __expf(-GAMMA * u * u);
    float r = __expf(KAF_C1 * u - 0.125f);
    float t = 0.f;
    #pragma unroll
    for (int d = 0; d < DD; d++) { t += a[d] * K; K *= r; r *= KAF_Q; }
    return t;
}

#define TB 16384                         // 128 rows x 64 halves x 2B
#define STAGE (2 * TB)                   // A, B
#define SMEM_TOTAL (2 * STAGE)           // 65536

__device__ __forceinline__ void load_chunk(uint32_t st,
                                           const __half* A, const __half* Bl,
                                           int m0, int nb, int kg, int tid) {
    uint32_t uA = st, uB = st + TB;
    #pragma unroll
    for (int it = 0; it < 4; it++) {
        int i = tid + it * 256;
        int r = i >> 3, c = i & 7;
        uint32_t so = SW128((uint32_t)(r * 128 + c * 16));
        cpa16(uA + so, &A[(m0 + r) * KK + kg + c * 8]);
        cpa16(uB + so, &Bl[(nb * 128 + r) * KK + kg + c * 8]);
    }
}

// grid (79, 2): rows bx*128, out cols by*128. K=512 in 8 chunks of 64.
__global__ __launch_bounds__(256) void k_gemm_fused(int layer,
                                                    const __half* __restrict__ A,
                                                    __half* __restrict__ AN,
                                                    const float* __restrict__ ew,
                                                    const float* __restrict__ bias,
                                                    const float* __restrict__ alpha,
                                                    float* __restrict__ out, int last) {
    extern __shared__ char smem[];
    uint32_t ubase = s2u(smem);
    const __half* Bl = gB + layer * CC * KK;

    int tid = threadIdx.x, wid = tid >> 5, lid = tid & 31;
    int m0 = blockIdx.x * 128;
    int nblk = blockIdx.y;
    int c0 = nblk * 128;
    int warp_m = (wid & 3) * 32;
    int warp_n = (wid >> 2) * 64;

    float acc[2][8][4];
    #pragma unroll
    for (int t = 0; t < 2; t++)
        #pragma unroll
        for (int n = 0; n < 8; n++)
            #pragma unroll
            for (int j = 0; j < 4; j++) acc[t][n][j] = 0.f;

    int g = lid >> 3, rid = lid & 7;

    load_chunk(ubase, A, Bl, m0, nblk, 0, tid);
    asm volatile("cp.async.commit_group;");

    for (int ch = 0; ch < 8; ch++) {
        if (ch < 7) {
            load_chunk(ubase + ((ch + 1) & 1) * STAGE, A, Bl, m0, nblk, (ch + 1) * 64, tid);
            asm volatile("cp.async.commit_group;");
            asm volatile("cp.async.wait_group 1;");
        } else {
            asm volatile("cp.async.wait_group 0;");
        }
        __syncthreads();

        uint32_t st = ubase + (ch & 1) * STAGE;
        uint32_t uA = st, uB = st + TB;

        #pragma unroll
        for (int ks = 0; ks < 4; ks++) {
            int kc2 = ks * 2;
            uint32_t b[8][2];
            #pragma unroll
            for (int p = 0; p < 4; p++) {
                int row = warp_n + p * 16 + ((g >> 1) ? 8 : 0) + rid;
                int chunk = kc2 + (g & 1);
                ldsm_x4(b[2 * p][0], b[2 * p][1], b[2 * p + 1][0], b[2 * p + 1][1],
                        uB + SW128((uint32_t)(row * 128 + chunk * 16)));
            }
            uint32_t a[2][4];
            #pragma unroll
            for (int t = 0; t < 2; t++) {
                int row = warp_m + t * 16 + ((g & 1) ? 8 : 0) + rid;
                int chunk = kc2 + (g >> 1);
                ldsm_x4(a[t][0], a[t][1], a[t][2], a[t][3],
                        uA + SW128((uint32_t)(row * 128 + chunk * 16)));
            }
            #pragma unroll
            for (int t = 0; t < 2; t++)
                #pragma unroll
                for (int n = 0; n < 8; n++)
                    mma16816(acc[t][n], a[t], b[n]);
        }
        __syncthreads();
    }

    // stage per-column params: ew0[128] ew1[128] bias[128] alpha[128*20]
    float* sP = (float*)smem;
    for (int i = tid; i < 128; i += 256) {
        int c = c0 + i;
        sP[i] = ew[c];
        sP[128 + i] = ew[CC + c];
        sP[256 + i] = bias[c];
    }
    for (int i = tid; i < 128 * DD; i += 256)
        sP[384 + i] = alpha[c0 * DD + i];
    __syncthreads();

    int qm = lid >> 2, qn = (lid & 3) * 2;
    uint32_t* ghi = (uint32_t*)AN;
    #pragma unroll
    for (int t = 0; t < 2; t++) {
        #pragma unroll
        for (int rr = 0; rr < 2; rr++) {
            int row = m0 + warp_m + t * 16 + qm + rr * 8;
            if (row >= NN) continue;
            float sc0 = g_sc0[row], sc1 = g_sc1[row];
            #pragma unroll
            for (int n = 0; n < 8; n++) {
                int lc = warp_n + n * 8 + qn;
                float s0 = acc[t][n][rr * 2]     + sc0 * sP[lc]     + sc1 * sP[128 + lc]     + sP[256 + lc];
                float s1 = acc[t][n][rr * 2 + 1] + sc0 * sP[lc + 1] + sc1 * sP[128 + lc + 1] + sP[256 + lc + 1];
                float r0 = kaf_eval(s0, &sP[384 + lc * DD]);
                float r1 = kaf_eval(s1, &sP[384 + (lc + 1) * DD]);
                if (last) {
                    *(float2*)&out[row * CC + c0 + lc] = make_float2(r0, r1);
                } else {
                    __half h0 = __float2half_rn(r0), h1 = __float2half_rn(r1);
                    uint32_t phi = ((uint32_t)*(uint16_t*)&h1 << 16) | *(uint16_t*)&h0;
                    ghi[row * 256 + 128 + ((c0 + lc) >> 1)] = phi;
                }
            }
        }
    }
}

// ---------------- launch ----------------
static cudaStream_t g_s2 = nullptr;
static cudaEvent_t g_evF = nullptr, g_evJ = nullptr;

extern "C" void kernel_launch(void* const* d_in, const int* in_sizes, int n_in,
                              void* d_out, int out_size) {
    const float* x       = (const float*)d_in[0];
    const int*   ei      = (const int*)d_in[1];
    const float* ea      = (const float*)d_in[2];
    const float* node_w  = (const float*)d_in[3];
    const float* edge_w  = (const float*)d_in[4];
    const float* neigh_w = (const float*)d_in[5];
    const float* bias    = (const float*)d_in[6];
    const float* alpha   = (const float*)d_in[7];
    float* out = (float*)d_out;

    if (!g_s2) {
        cudaStreamCreateWithFlags(&g_s2, cudaStreamNonBlocking);
        cudaEventCreateWithFlags(&g_evF, cudaEventDisableTiming);
        cudaEventCreateWithFlags(&g_evJ, cudaEventDisableTiming);
        cudaFuncSetAttribute(k_gemm_fused, cudaFuncAttributeMaxDynamicSharedMemorySize, SMEM_TOTAL);
    }

    __half *a0, *a1;
    cudaGetSymbolAddress((void**)&a0, gA0);
    cudaGetSymbolAddress((void**)&a1, gA1);
    __half* AB[2] = {a0, a1};

    // fork: CSR chain on side stream
    cudaEventRecord(g_evF, 0);
    cudaStreamWaitEvent(g_s2, g_evF, 0);
    k_zero<<<(NN + 255) / 256, 256, 0, g_s2>>>();
    k_count<<<(EE + 255) / 256, 256, 0, g_s2>>>(ei, ea);
    k_scan<<<1, 1024, 0, g_s2>>>();
    k_scatter<<<(EE + 255) / 256, 256, 0, g_s2>>>(ei);
    cudaEventRecord(g_evJ, g_s2);

    // main: dense prep
    k_split_x<<<(NN * CC + 255) / 256, 256>>>(x);
    k_prep_B<<<(LL * CC * KK + 255) / 256, 256>>>(neigh_w, node_w);
    cudaStreamWaitEvent(0, g_evJ, 0);

    dim3 gg(NT, 2);
    for (int l = 0; l < LL; l++) {
        int b = l & 1;
        k_gather<<<(NN + 7) / 8, 256>>>(AB[b], AB[b]);
        k_gemm_fused<<<gg, 256, SMEM_TOTAL>>>(l, AB[b], AB[b ^ 1],
                                              edge_w + l * 2 * CC, bias + l * CC,
                                              alpha + l * CC * DD, out, (l == LL - 1) ? 1 : 0);
    }
}